// round 14
// baseline (speedup 1.0000x reference)
#include <cuda_runtime.h>
#include <math.h>

#define FULL 0xFFFFFFFFu
typedef unsigned long long u64;

// ---- packed f32x2 helpers (sm_103a) ------------------------------------
__device__ __forceinline__ u64 pk2(float lo, float hi) {
    u64 r; asm("mov.b64 %0, {%1, %2};" : "=l"(r) : "f"(lo), "f"(hi)); return r;
}
__device__ __forceinline__ float lo2(u64 x) { return __uint_as_float((unsigned)x); }
__device__ __forceinline__ float hi2(u64 x) { return __uint_as_float((unsigned)(x >> 32)); }
__device__ __forceinline__ u64 fma2(u64 a, u64 b, u64 c) {
    u64 d; asm("fma.rn.f32x2 %0, %1, %2, %3;" : "=l"(d) : "l"(a), "l"(b), "l"(c)); return d;
}
__device__ __forceinline__ u64 mul2(u64 a, u64 b) {
    u64 d; asm("mul.rn.f32x2 %0, %1, %2;" : "=l"(d) : "l"(a), "l"(b)); return d;
}
__device__ __forceinline__ u64 add2(u64 a, u64 b) {
    u64 d; asm("add.rn.f32x2 %0, %1, %2;" : "=l"(d) : "l"(a), "l"(b)); return d;
}
__device__ __forceinline__ u64 shfl64(u64 x, int src) {
    unsigned lo = (unsigned)x, hi = (unsigned)(x >> 32);
    lo = __shfl_sync(FULL, lo, src);
    hi = __shfl_sync(FULL, hi, src);
    return ((u64)hi << 32) | (u64)lo;
}
__device__ __forceinline__ u64 shfl64x(u64 x, int mask) {
    unsigned lo = (unsigned)x, hi = (unsigned)(x >> 32);
    lo = __shfl_xor_sync(FULL, lo, mask);
    hi = __shfl_xor_sync(FULL, hi, mask);
    return ((u64)hi << 32) | (u64)lo;
}

// One 64x64 SPD matrix per 64-thread block (2 warps). Warp w owns ROWS
// 32w..32w+31; lane k holds that half of two columns (u at ring pos k,
// v at pos k+32), 16 x f32x2 each. Halving per-thread state (64 data regs
// vs 128) lifts the occupancy cap that pinned the 1-warp design at 12
// warps/SM / 57% issue for 5 rounds (R9-R13 all within +-5% of 2850).
// The pairing dot is cross-warp: partial -> STS.64 -> one __syncthreads
// -> LDS.64 partner -> add, parity-double-buffered (slot reuse is two
// exchanges later, with a bar in between -> single bar per exchange is
// sufficient). All scalars (du, dv, angle, ballot) are computed
// redundantly and identically in both warps -> no divergence hazards.
// Locked by measurement: SHFL ring exchange; standard (c,s) rotations;
// cap 16 sweeps (10 -> rel_err 0.099); ballot-gated skip from sweep 4;
// thr 2e-8 (err ~ 3.3*sqrt(thr), 5 data points).
__global__ __launch_bounds__(64, 8) void logeig_jacobi(const float* __restrict__ P,
                                                       float* __restrict__ X,
                                                       int nmat) {
    const int m = blockIdx.x;
    if (m >= nmat) return;
    const int tid = threadIdx.x;
    const int k = tid & 31;
    const int w = tid >> 5;            // 0: rows 0-31, 1: rows 32-63
    const int rb = w << 5;
    const int pw = w ^ 1;              // partner warp
    const float* __restrict__ Pm = P + (size_t)m * 4096;
    float* __restrict__ Xm = X + (size_t)m * 4096;

    __shared__ __align__(16) float POOL[64 * 66];
    __shared__ float gw[64];
    __shared__ u64 xbuf[2][2][32];
    int par = 0;

    u64 U[16], V[16];
#pragma unroll
    for (int j = 0; j < 16; ++j) {
        U[j] = pk2(Pm[(rb + 2 * j) * 64 + k],      Pm[(rb + 2 * j + 1) * 64 + k]);
        V[j] = pk2(Pm[(rb + 2 * j) * 64 + k + 32], Pm[(rb + 2 * j + 1) * 64 + k + 32]);
    }

    float du = 0.f, dv = 0.f;

    for (int sweep = 0; sweep < 16; ++sweep) {
        const bool gated = (sweep >= 4);

        // exact norms: per-warp partials, cross-warp sum
        {
            u64 a0 = 0, a1 = 0, b0 = 0, b1 = 0;
#pragma unroll
            for (int j = 0; j < 16; j += 2) {
                a0 = fma2(U[j], U[j], a0);     a1 = fma2(U[j + 1], U[j + 1], a1);
                b0 = fma2(V[j], V[j], b0);     b1 = fma2(V[j + 1], V[j + 1], b1);
            }
            u64 a = add2(a0, a1), b = add2(b0, b1);
            float pdu = lo2(a) + hi2(a), pdv = lo2(b) + hi2(b);
            xbuf[par][w][k] = pk2(pdu, pdv);
            __syncthreads();
            u64 o = xbuf[par][pw][k]; par ^= 1;
            du = pdu + lo2(o);
            dv = pdv + hi2(o);
        }

        unsigned any = 0u;
        for (int g = 32; g >= 1; g >>= 1) {
            const int src = (k & ~(g - 1)) | ((k + 1) & (g - 1));

            // fresh pairing dot at level start (cross-warp)
            float x;
            {
                u64 x0 = 0, x1 = 0;
#pragma unroll
                for (int j = 0; j < 16; ++j) {
                    if (j & 1) x1 = fma2(U[j], V[j], x1);
                    else       x0 = fma2(U[j], V[j], x0);
                }
                u64 s2 = add2(x0, x1);
                float xs = lo2(s2) + hi2(s2);
                xbuf[par][w][k] = pk2(xs, xs);
                __syncthreads();
                u64 o = xbuf[par][pw][k]; par ^= 1;
                x = xs + lo2(o);
            }

            for (int r = 0; r < g; ++r) {
                bool rot = (x * x > 2e-8f * du * dv);
                unsigned bal;
                if (gated) {
                    bal = __ballot_sync(FULL, rot);   // identical in both warps
                    any |= bal;
                } else {
                    bal = FULL;
                }

                u64 x0 = 0, x1 = 0;
                if (bal) {
                    float a = dv - du;
                    float b = 2.0f * x;
                    float D = sqrtf(fmaf(a, a, b * b));
                    float t = __fdividef(b, a + copysignf(D, a));
                    if (!rot) t = 0.0f;
                    float c = rsqrtf(fmaf(t, t, 1.0f));
                    float s = t * c;

                    float ndu = fmaf(-t, x, du);
                    float ndv = fmaf( t, x, dv);

                    u64 cc = pk2(c, c), ss = pk2(s, s), ns = pk2(-s, -s);
#pragma unroll
                    for (int j = 0; j < 16; ++j) {
                        u64 un = fma2(cc, U[j], mul2(ns, V[j]));
                        u64 vn = fma2(cc, V[j], mul2(ss, U[j]));
                        U[j] = un;
                        V[j] = shfl64(vn, src);
                        if (j & 1) x1 = fma2(un, V[j], x1);
                        else       x0 = fma2(un, V[j], x0);
                    }
                    du = ndu;
                    dv = __shfl_sync(FULL, ndv, src);
                } else {
#pragma unroll
                    for (int j = 0; j < 16; ++j) {
                        V[j] = shfl64(V[j], src);
                        if (j & 1) x1 = fma2(U[j], V[j], x1);
                        else       x0 = fma2(U[j], V[j], x0);
                    }
                    dv = __shfl_sync(FULL, dv, src);
                }
                // cross-warp sum of the fused next-pairing dot
                u64 s2 = add2(x0, x1);
                float xs = lo2(s2) + hi2(s2);
                xbuf[par][w][k] = pk2(xs, xs);
                __syncthreads();
                u64 o = xbuf[par][pw][k]; par ^= 1;
                x = xs + lo2(o);
            }

            // split: lower half-lanes keep u-set, upper keep v-set (per warp)
            if (g > 1) {
                const int h = g >> 1;
                const bool low = (k & h) == 0;
#pragma unroll
                for (int j = 0; j < 16; ++j) {
                    u64 pu = shfl64x(U[j], h);
                    u64 pv = shfl64x(V[j], h);
                    if (low) V[j] = pu; else U[j] = pv;
                }
                float pdu = __shfl_xor_sync(FULL, du, h);
                float pdv = __shfl_xor_sync(FULL, dv, h);
                if (low) dv = pdu; else du = pdv;
            }
        }
        if (gated && any == 0u) break;
    }

    // final norms (cross-warp) -> log weights
    float fdu, fdv;
    {
        u64 a0 = 0, a1 = 0, b0 = 0, b1 = 0;
#pragma unroll
        for (int j = 0; j < 16; j += 2) {
            a0 = fma2(U[j], U[j], a0);     a1 = fma2(U[j + 1], U[j + 1], a1);
            b0 = fma2(V[j], V[j], b0);     b1 = fma2(V[j + 1], V[j + 1], b1);
        }
        u64 a = add2(a0, a1), b = add2(b0, b1);
        float pdu = lo2(a) + hi2(a), pdv = lo2(b) + hi2(b);
        xbuf[par][w][k] = pk2(pdu, pdv);
        __syncthreads();
        u64 o = xbuf[par][pw][k]; par ^= 1;
        fdu = pdu + lo2(o);
        fdv = pdv + hi2(o);
    }

    // stage W[col][component]; thread (w,k) writes its half-rows of 2 cols
    float (*W)[66] = (float (*)[66])POOL;
    {
        u64* ru = (u64*)&W[k][rb];
        u64* rv = (u64*)&W[k + 32][rb];
#pragma unroll
        for (int j = 0; j < 16; ++j) { ru[j] = U[j]; rv[j] = V[j]; }
    }
    if (w == 0) {
        gw[k]      = 0.5f * __logf(fdu) / fdu;
        gw[k + 32] = 0.5f * __logf(fdv) / fdv;
    }
    __syncthreads();

    // X = sum_p g_p w_p w_p^T ; thread (w,k) emits rows rb..rb+31 of
    // columns k and k+32
#pragma unroll
    for (int half = 0; half < 2; ++half) {
        const int col = k + 32 * half;
        u64 acc[16];
#pragma unroll
        for (int j = 0; j < 16; ++j) acc[j] = 0ull;
        for (int p = 0; p < 64; ++p) {
            float sp = gw[p] * W[p][col];
            u64 sp2 = pk2(sp, sp);
            const u64* row = (const u64*)&W[p][rb];
#pragma unroll
            for (int j = 0; j < 16; ++j) acc[j] = fma2(sp2, row[j], acc[j]);
        }
#pragma unroll
        for (int j = 0; j < 16; ++j) {
            Xm[(rb + 2 * j) * 64 + col]     = lo2(acc[j]);
            Xm[(rb + 2 * j + 1) * 64 + col] = hi2(acc[j]);
        }
    }
}

extern "C" void kernel_launch(void* const* d_in, const int* in_sizes, int n_in,
                              void* d_out, int out_size) {
    const float* P = (const float*)d_in[0];
    float* X = (float*)d_out;
    int nmat = in_sizes[0] / 4096;
    logeig_jacobi<<<nmat, 64>>>(P, X, nmat);
}

// round 15
// speedup vs baseline: 1.0962x; 1.0962x over previous
#include <cuda_runtime.h>
#include <math.h>

#define FULL 0xFFFFFFFFu
typedef unsigned long long u64;

// ---- packed f32x2 helpers (sm_103a) ------------------------------------
__device__ __forceinline__ u64 pk2(float lo, float hi) {
    u64 r; asm("mov.b64 %0, {%1, %2};" : "=l"(r) : "f"(lo), "f"(hi)); return r;
}
__device__ __forceinline__ float lo2(u64 x) { return __uint_as_float((unsigned)x); }
__device__ __forceinline__ float hi2(u64 x) { return __uint_as_float((unsigned)(x >> 32)); }
__device__ __forceinline__ u64 fma2(u64 a, u64 b, u64 c) {
    u64 d; asm("fma.rn.f32x2 %0, %1, %2, %3;" : "=l"(d) : "l"(a), "l"(b), "l"(c)); return d;
}
__device__ __forceinline__ u64 mul2(u64 a, u64 b) {
    u64 d; asm("mul.rn.f32x2 %0, %1, %2;" : "=l"(d) : "l"(a), "l"(b)); return d;
}
__device__ __forceinline__ u64 add2(u64 a, u64 b) {
    u64 d; asm("add.rn.f32x2 %0, %1, %2;" : "=l"(d) : "l"(a), "l"(b)); return d;
}
__device__ __forceinline__ u64 shfl64(u64 x, int src) {
    unsigned lo = (unsigned)x, hi = (unsigned)(x >> 32);
    lo = __shfl_sync(FULL, lo, src);
    hi = __shfl_sync(FULL, hi, src);
    return ((u64)hi << 32) | (u64)lo;
}
__device__ __forceinline__ u64 shfl64x(u64 x, int mask) {
    unsigned lo = (unsigned)x, hi = (unsigned)(x >> 32);
    lo = __shfl_xor_sync(FULL, lo, mask);
    hi = __shfl_xor_sync(FULL, hi, mask);
    return ((u64)hi << 32) | (u64)lo;
}
__device__ __forceinline__ float red2(u64 a, u64 b, u64 c, u64 d) {
    u64 s = add2(add2(a, b), add2(c, d));
    return lo2(s) + hi2(s);
}

// One warp per 64x64 SPD matrix. Lane k holds two columns (u, v) packed as
// 32 x f32x2. One-sided Jacobi, recursive-halving tournament, SHFL ring
// exchange, fused next-pairing dot, standard (c,s) rotations.
// This is the R12 structure (best measured: 2847us) with the two knobs
// moved along their verified response curves.
// Design space closed by measurement:
//  - SHFL exchange (shared STS/LDS.128 doubles crossbar traffic: -26%, R9)
//  - standard rotations (deferred-scale: spills (R10) or scalar-chain -5% (R11))
//  - single warp per matrix (2-warp split: redundant scalar work + per-round
//    bar overhead outruns the occupancy gain: +10%, R14)
//  - dot-elimination restructure: I-cache/branch cost > slot savings (R13)
//  - (32,12) launch bounds ((32,13) spills U/V: 4x, R7)
//  - cap 16 sweeps (cap 10: rel_err 0.099, R4)
//  - err = ~3.3*sqrt(thr), verified 5x: 1e-10->3.2e-5, 1e-9->9.9e-5,
//    1e-8->3.28e-4, 2e-8->4.72e-4, 3e-8->5.84e-4 (R13, passing)
//  - thr 3e-8, ballot gating from sweep 3
__global__ __launch_bounds__(32, 12) void logeig_jacobi(const float* __restrict__ P,
                                                        float* __restrict__ X,
                                                        int nmat) {
    const int m = blockIdx.x;
    if (m >= nmat) return;
    const int k = threadIdx.x;
    const float* __restrict__ Pm = P + (size_t)m * 4096;
    float* __restrict__ Xm = X + (size_t)m * 4096;

    u64 U[32], V[32];
#pragma unroll
    for (int j = 0; j < 32; ++j) {
        U[j] = pk2(Pm[(2 * j) * 64 + k],        Pm[(2 * j + 1) * 64 + k]);
        V[j] = pk2(Pm[(2 * j) * 64 + (k + 32)], Pm[(2 * j + 1) * 64 + (k + 32)]);
    }

    float du = 0.f, dv = 0.f;

    for (int sweep = 0; sweep < 16; ++sweep) {
        const bool gated = (sweep >= 3);

        // exact norms at sweep start
        {
            u64 a0 = 0, a1 = 0, b0 = 0, b1 = 0;
#pragma unroll
            for (int j = 0; j < 32; j += 2) {
                a0 = fma2(U[j], U[j], a0);     a1 = fma2(U[j + 1], U[j + 1], a1);
                b0 = fma2(V[j], V[j], b0);     b1 = fma2(V[j + 1], V[j + 1], b1);
            }
            u64 a = add2(a0, a1), b = add2(b0, b1);
            du = lo2(a) + hi2(a);
            dv = lo2(b) + hi2(b);
        }

        unsigned any = 0u;
        for (int g = 32; g >= 1; g >>= 1) {
            const int src = (k & ~(g - 1)) | ((k + 1) & (g - 1));

            // fresh dot at level start
            float x;
            {
                u64 x0 = 0, x1 = 0, x2 = 0, x3 = 0;
#pragma unroll
                for (int j = 0; j < 32; j += 4) {
                    x0 = fma2(U[j],     V[j],     x0);
                    x1 = fma2(U[j + 1], V[j + 1], x1);
                    x2 = fma2(U[j + 2], V[j + 2], x2);
                    x3 = fma2(U[j + 3], V[j + 3], x3);
                }
                x = red2(x0, x1, x2, x3);
            }

            for (int r = 0; r < g; ++r) {
                bool rot = (x * x > 3e-8f * du * dv);
                unsigned bal;
                if (gated) {
                    bal = __ballot_sync(FULL, rot);
                    any |= bal;
                } else {
                    bal = FULL;
                }

                u64 x0 = 0, x1 = 0, x2 = 0, x3 = 0;
                if (bal) {
                    // full path: one-division angle, rotate, fused next dot
                    float a = dv - du;
                    float b = 2.0f * x;
                    float D = sqrtf(fmaf(a, a, b * b));
                    float t = __fdividef(b, a + copysignf(D, a));
                    if (!rot) t = 0.0f;                   // c=1, s=0 fallthrough
                    float c = rsqrtf(fmaf(t, t, 1.0f));
                    float s = t * c;

                    float ndu = fmaf(-t, x, du);
                    float ndv = fmaf( t, x, dv);

                    u64 cc = pk2(c, c), ss = pk2(s, s), ns = pk2(-s, -s);
#pragma unroll
                    for (int j = 0; j < 32; ++j) {
                        u64 un = fma2(cc, U[j], mul2(ns, V[j]));
                        u64 vn = fma2(cc, V[j], mul2(ss, U[j]));
                        U[j] = un;
                        V[j] = shfl64(vn, src);
                        if ((j & 3) == 0)      x0 = fma2(un, V[j], x0);
                        else if ((j & 3) == 1) x1 = fma2(un, V[j], x1);
                        else if ((j & 3) == 2) x2 = fma2(un, V[j], x2);
                        else                   x3 = fma2(un, V[j], x3);
                    }
                    du = ndu;
                    dv = __shfl_sync(FULL, ndv, src);
                } else {
                    // skip path: no lane rotates -> advance pairing + dot only
#pragma unroll
                    for (int j = 0; j < 32; ++j) {
                        V[j] = shfl64(V[j], src);
                        if ((j & 3) == 0)      x0 = fma2(U[j], V[j], x0);
                        else if ((j & 3) == 1) x1 = fma2(U[j], V[j], x1);
                        else if ((j & 3) == 2) x2 = fma2(U[j], V[j], x2);
                        else                   x3 = fma2(U[j], V[j], x3);
                    }
                    dv = __shfl_sync(FULL, dv, src);
                }
                x = red2(x0, x1, x2, x3);
            }

            // split: lower half-lanes keep u-set, upper keep v-set
            if (g > 1) {
                const int h = g >> 1;
                const bool low = (k & h) == 0;
#pragma unroll
                for (int j = 0; j < 32; ++j) {
                    u64 pu = shfl64x(U[j], h);
                    u64 pv = shfl64x(V[j], h);
                    if (low) V[j] = pu; else U[j] = pv;
                }
                float pdu = __shfl_xor_sync(FULL, du, h);
                float pdv = __shfl_xor_sync(FULL, dv, h);
                if (low) dv = pdu; else du = pdv;
            }
        }
        if (gated && any == 0u) break;
    }

    // exact final norms -> log weights  g_p = 0.5*log(d_p)/d_p
    float fdu, fdv;
    {
        u64 a0 = 0, a1 = 0, b0 = 0, b1 = 0;
#pragma unroll
        for (int j = 0; j < 32; j += 2) {
            a0 = fma2(U[j], U[j], a0);     a1 = fma2(U[j + 1], U[j + 1], a1);
            b0 = fma2(V[j], V[j], b0);     b1 = fma2(V[j + 1], V[j + 1], b1);
        }
        u64 a = add2(a0, a1), b = add2(b0, b1);
        fdu = lo2(a) + hi2(a);
        fdv = lo2(b) + hi2(b);
    }

    __shared__ __align__(16) float W[64][66];
    __shared__ float gw[64];
#pragma unroll
    for (int j = 0; j < 32; ++j) {
        W[k][2 * j]          = lo2(U[j]);
        W[k][2 * j + 1]      = hi2(U[j]);
        W[k + 32][2 * j]     = lo2(V[j]);
        W[k + 32][2 * j + 1] = hi2(V[j]);
    }
    gw[k]      = 0.5f * __logf(fdu) / fdu;
    gw[k + 32] = 0.5f * __logf(fdv) / fdv;
    __syncwarp();

    // X = sum_p g_p w_p w_p^T ; lane k emits columns k and k+32, in
    // 16-wide row quarters to keep peak register pressure under the cap.
#pragma unroll
    for (int half = 0; half < 2; ++half) {
        const int col = k + 32 * half;
#pragma unroll
        for (int q = 0; q < 2; ++q) {
            u64 acc[16];
#pragma unroll
            for (int j = 0; j < 16; ++j) acc[j] = 0ull;
            for (int p = 0; p < 64; ++p) {
                float sp = gw[p] * W[p][col];
                u64 sp2 = pk2(sp, sp);
                const u64* row = (const u64*)&W[p][0] + 16 * q;
#pragma unroll
                for (int j = 0; j < 16; ++j) acc[j] = fma2(sp2, row[j], acc[j]);
            }
#pragma unroll
            for (int j = 0; j < 16; ++j) {
                Xm[(32 * q + 2 * j) * 64 + col]     = lo2(acc[j]);
                Xm[(32 * q + 2 * j + 1) * 64 + col] = hi2(acc[j]);
            }
        }
    }
}

extern "C" void kernel_launch(void* const* d_in, const int* in_sizes, int n_in,
                              void* d_out, int out_size) {
    const float* P = (const float*)d_in[0];
    float* X = (float*)d_out;
    int nmat = in_sizes[0] / 4096;
    logeig_jacobi<<<nmat, 32>>>(P, X, nmat);
}

// round 16
// speedup vs baseline: 1.1304x; 1.0312x over previous
#include <cuda_runtime.h>
#include <math.h>

#define FULL 0xFFFFFFFFu
typedef unsigned long long u64;

// ---- packed f32x2 helpers (sm_103a) ------------------------------------
__device__ __forceinline__ u64 pk2(float lo, float hi) {
    u64 r; asm("mov.b64 %0, {%1, %2};" : "=l"(r) : "f"(lo), "f"(hi)); return r;
}
__device__ __forceinline__ float lo2(u64 x) { return __uint_as_float((unsigned)x); }
__device__ __forceinline__ float hi2(u64 x) { return __uint_as_float((unsigned)(x >> 32)); }
__device__ __forceinline__ u64 fma2(u64 a, u64 b, u64 c) {
    u64 d; asm("fma.rn.f32x2 %0, %1, %2, %3;" : "=l"(d) : "l"(a), "l"(b), "l"(c)); return d;
}
__device__ __forceinline__ u64 mul2(u64 a, u64 b) {
    u64 d; asm("mul.rn.f32x2 %0, %1, %2;" : "=l"(d) : "l"(a), "l"(b)); return d;
}
__device__ __forceinline__ u64 add2(u64 a, u64 b) {
    u64 d; asm("add.rn.f32x2 %0, %1, %2;" : "=l"(d) : "l"(a), "l"(b)); return d;
}
__device__ __forceinline__ u64 shfl64(u64 x, int src) {
    unsigned lo = (unsigned)x, hi = (unsigned)(x >> 32);
    lo = __shfl_sync(FULL, lo, src);
    hi = __shfl_sync(FULL, hi, src);
    return ((u64)hi << 32) | (u64)lo;
}
__device__ __forceinline__ u64 shfl64x(u64 x, int mask) {
    unsigned lo = (unsigned)x, hi = (unsigned)(x >> 32);
    lo = __shfl_xor_sync(FULL, lo, mask);
    hi = __shfl_xor_sync(FULL, hi, mask);
    return ((u64)hi << 32) | (u64)lo;
}
__device__ __forceinline__ float red2(u64 a, u64 b, u64 c, u64 d) {
    u64 s = add2(add2(a, b), add2(c, d));
    return lo2(s) + hi2(s);
}

// One warp per 64x64 SPD matrix. Lane k holds two columns (u, v) packed as
// 32 x f32x2. One-sided Jacobi, recursive-halving tournament, SHFL ring
// exchange, fused next-pairing dot, standard (c,s) rotations.
// R12 structure (best: 2847us) + ONE change: the level-split now moves only
// the value each pair actually exchanges (send = hi?U:V, one shfl64/j)
// instead of shuffling both U and V and discarding half -- halves split
// SHFL traffic (-12% of MIO, the 60%-busy co-binding pipe), paying with
// SELs on the 15%-busy ALU pipe. Bit-identical arithmetic to R12.
// Design space closed by measurement:
//  - SHFL exchange (shared STS/LDS.128 doubles crossbar traffic: -26%, R9)
//  - standard rotations (deferred-scale: spills (R10) / scalar chain -5% (R11))
//  - single warp per matrix (2-warp split: +10%, R14)
//  - dot-elimination restructure: I-cache cost > slot savings (R13)
//  - (32,12) bounds ((32,13) spills: 4x, R7); cap 16 sweeps (10: 0.099, R4)
//  - err = 3.3*sqrt(thr) verified 6x; time flat across thr 1e-8..3e-8 (R15)
//    => thr 2e-8 (rel_err 4.72e-4, margin 2.1x), ballot gating from sweep 4
__global__ __launch_bounds__(32, 12) void logeig_jacobi(const float* __restrict__ P,
                                                        float* __restrict__ X,
                                                        int nmat) {
    const int m = blockIdx.x;
    if (m >= nmat) return;
    const int k = threadIdx.x;
    const float* __restrict__ Pm = P + (size_t)m * 4096;
    float* __restrict__ Xm = X + (size_t)m * 4096;

    u64 U[32], V[32];
#pragma unroll
    for (int j = 0; j < 32; ++j) {
        U[j] = pk2(Pm[(2 * j) * 64 + k],        Pm[(2 * j + 1) * 64 + k]);
        V[j] = pk2(Pm[(2 * j) * 64 + (k + 32)], Pm[(2 * j + 1) * 64 + (k + 32)]);
    }

    float du = 0.f, dv = 0.f;

    for (int sweep = 0; sweep < 16; ++sweep) {
        const bool gated = (sweep >= 4);

        // exact norms at sweep start
        {
            u64 a0 = 0, a1 = 0, b0 = 0, b1 = 0;
#pragma unroll
            for (int j = 0; j < 32; j += 2) {
                a0 = fma2(U[j], U[j], a0);     a1 = fma2(U[j + 1], U[j + 1], a1);
                b0 = fma2(V[j], V[j], b0);     b1 = fma2(V[j + 1], V[j + 1], b1);
            }
            u64 a = add2(a0, a1), b = add2(b0, b1);
            du = lo2(a) + hi2(a);
            dv = lo2(b) + hi2(b);
        }

        unsigned any = 0u;
        for (int g = 32; g >= 1; g >>= 1) {
            const int src = (k & ~(g - 1)) | ((k + 1) & (g - 1));

            // fresh dot at level start
            float x;
            {
                u64 x0 = 0, x1 = 0, x2 = 0, x3 = 0;
#pragma unroll
                for (int j = 0; j < 32; j += 4) {
                    x0 = fma2(U[j],     V[j],     x0);
                    x1 = fma2(U[j + 1], V[j + 1], x1);
                    x2 = fma2(U[j + 2], V[j + 2], x2);
                    x3 = fma2(U[j + 3], V[j + 3], x3);
                }
                x = red2(x0, x1, x2, x3);
            }

            for (int r = 0; r < g; ++r) {
                bool rot = (x * x > 2e-8f * du * dv);
                unsigned bal;
                if (gated) {
                    bal = __ballot_sync(FULL, rot);
                    any |= bal;
                } else {
                    bal = FULL;
                }

                u64 x0 = 0, x1 = 0, x2 = 0, x3 = 0;
                if (bal) {
                    // full path: one-division angle, rotate, fused next dot
                    float a = dv - du;
                    float b = 2.0f * x;
                    float D = sqrtf(fmaf(a, a, b * b));
                    float t = __fdividef(b, a + copysignf(D, a));
                    if (!rot) t = 0.0f;                   // c=1, s=0 fallthrough
                    float c = rsqrtf(fmaf(t, t, 1.0f));
                    float s = t * c;

                    float ndu = fmaf(-t, x, du);
                    float ndv = fmaf( t, x, dv);

                    u64 cc = pk2(c, c), ss = pk2(s, s), ns = pk2(-s, -s);
#pragma unroll
                    for (int j = 0; j < 32; ++j) {
                        u64 un = fma2(cc, U[j], mul2(ns, V[j]));
                        u64 vn = fma2(cc, V[j], mul2(ss, U[j]));
                        U[j] = un;
                        V[j] = shfl64(vn, src);
                        if ((j & 3) == 0)      x0 = fma2(un, V[j], x0);
                        else if ((j & 3) == 1) x1 = fma2(un, V[j], x1);
                        else if ((j & 3) == 2) x2 = fma2(un, V[j], x2);
                        else                   x3 = fma2(un, V[j], x3);
                    }
                    du = ndu;
                    dv = __shfl_sync(FULL, ndv, src);
                } else {
                    // skip path: no lane rotates -> advance pairing + dot only
#pragma unroll
                    for (int j = 0; j < 32; ++j) {
                        V[j] = shfl64(V[j], src);
                        if ((j & 3) == 0)      x0 = fma2(U[j], V[j], x0);
                        else if ((j & 3) == 1) x1 = fma2(U[j], V[j], x1);
                        else if ((j & 3) == 2) x2 = fma2(U[j], V[j], x2);
                        else                   x3 = fma2(U[j], V[j], x3);
                    }
                    dv = __shfl_sync(FULL, dv, src);
                }
                x = red2(x0, x1, x2, x3);
            }

            // split: each pair exchanges exactly ONE value per j --
            // high lanes send U (received into low's V), low lanes send V
            // (received into high's U). Halves split shuffle traffic.
            if (g > 1) {
                const int h = g >> 1;
                const bool hi = (k & h) != 0;
#pragma unroll
                for (int j = 0; j < 32; ++j) {
                    u64 snd = hi ? U[j] : V[j];
                    u64 rcv = shfl64x(snd, h);
                    if (hi) U[j] = rcv; else V[j] = rcv;
                }
                float snds = hi ? du : dv;
                float rcvs = __shfl_xor_sync(FULL, snds, h);
                if (hi) du = rcvs; else dv = rcvs;
            }
        }
        if (gated && any == 0u) break;
    }

    // exact final norms -> log weights  g_p = 0.5*log(d_p)/d_p
    float fdu, fdv;
    {
        u64 a0 = 0, a1 = 0, b0 = 0, b1 = 0;
#pragma unroll
        for (int j = 0; j < 32; j += 2) {
            a0 = fma2(U[j], U[j], a0);     a1 = fma2(U[j + 1], U[j + 1], a1);
            b0 = fma2(V[j], V[j], b0);     b1 = fma2(V[j + 1], V[j + 1], b1);
        }
        u64 a = add2(a0, a1), b = add2(b0, b1);
        fdu = lo2(a) + hi2(a);
        fdv = lo2(b) + hi2(b);
    }

    __shared__ __align__(16) float W[64][66];
    __shared__ float gw[64];
#pragma unroll
    for (int j = 0; j < 32; ++j) {
        W[k][2 * j]          = lo2(U[j]);
        W[k][2 * j + 1]      = hi2(U[j]);
        W[k + 32][2 * j]     = lo2(V[j]);
        W[k + 32][2 * j + 1] = hi2(V[j]);
    }
    gw[k]      = 0.5f * __logf(fdu) / fdu;
    gw[k + 32] = 0.5f * __logf(fdv) / fdv;
    __syncwarp();

    // X = sum_p g_p w_p w_p^T ; lane k emits columns k and k+32, in
    // 16-wide row quarters to keep peak register pressure under the cap.
#pragma unroll
    for (int half = 0; half < 2; ++half) {
        const int col = k + 32 * half;
#pragma unroll
        for (int q = 0; q < 2; ++q) {
            u64 acc[16];
#pragma unroll
            for (int j = 0; j < 16; ++j) acc[j] = 0ull;
            for (int p = 0; p < 64; ++p) {
                float sp = gw[p] * W[p][col];
                u64 sp2 = pk2(sp, sp);
                const u64* row = (const u64*)&W[p][0] + 16 * q;
#pragma unroll
                for (int j = 0; j < 16; ++j) acc[j] = fma2(sp2, row[j], acc[j]);
            }
#pragma unroll
            for (int j = 0; j < 16; ++j) {
                Xm[(32 * q + 2 * j) * 64 + col]     = lo2(acc[j]);
                Xm[(32 * q + 2 * j + 1) * 64 + col] = hi2(acc[j]);
            }
        }
    }
}

extern "C" void kernel_launch(void* const* d_in, const int* in_sizes, int n_in,
                              void* d_out, int out_size) {
    const float* P = (const float*)d_in[0];
    float* X = (float*)d_out;
    int nmat = in_sizes[0] / 4096;
    logeig_jacobi<<<nmat, 32>>>(P, X, nmat);
}